// round 2
// baseline (speedup 1.0000x reference)
#include <cuda_runtime.h>
#include <cuda_bf16.h>
#include <cstdint>

// ---------------- problem dims ----------------
#define MDIM 8192
#define KDIM 4096
#define NDIM 16384

// ---------------- GEMM tiling ----------------
#define BM 128
#define BN 128
#define BK 128
#define STAGES 4
#define A_ST (BM * BK)              // 16384 bytes (int8)
#define B_ST (BN * BK)              // 16384 bytes
#define STG_BYTES (A_ST + B_ST)     // 32768
#define SMEM_TOTAL (STAGES * STG_BYTES)  // 131072
#define KTILES (KDIM / BK)          // 32
#define NT_M (MDIM / BM)            // 64
#define NT_N (NDIM / BN)            // 128

// ---------------- device scratch ----------------
__device__ float g_xmax[KDIM];
__device__ float g_wmax[KDIM];
__device__ float g_smooth[KDIM];
__device__ float g_xs[MDIM];
__device__ float g_ws[NDIM];
__device__ int8_t g_xq8[(size_t)MDIM * KDIM];  // 32 MB row-major
__device__ int8_t g_wq8[(size_t)NDIM * KDIM];  // 64 MB row-major

// ---------------- PTX helpers ----------------
__device__ __forceinline__ uint32_t smem_u32(const void* p) {
    uint32_t a;
    asm("{ .reg .u64 t; cvta.to.shared.u64 t, %1; cvt.u32.u64 %0, t; }" : "=r"(a) : "l"(p));
    return a;
}

__device__ __forceinline__ void cp_async16(uint32_t saddr, const void* gaddr) {
    asm volatile("cp.async.cg.shared.global [%0], [%1], 16;" :: "r"(saddr), "l"(gaddr)
                 : "memory");
}
#define CP_COMMIT() asm volatile("cp.async.commit_group;" ::: "memory")
#define CP_WAIT(n) asm volatile("cp.async.wait_group %0;" :: "n"(n) : "memory")

__device__ __forceinline__ void ldm_x4(uint32_t& r0, uint32_t& r1, uint32_t& r2, uint32_t& r3,
                                       uint32_t addr) {
    asm volatile("ldmatrix.sync.aligned.m8n8.x4.shared.b16 {%0,%1,%2,%3}, [%4];"
                 : "=r"(r0), "=r"(r1), "=r"(r2), "=r"(r3) : "r"(addr));
}

__device__ __forceinline__ void imma16832(int* c, const uint32_t* a, uint32_t b0, uint32_t b1) {
    asm volatile(
        "mma.sync.aligned.m16n8k32.row.col.s32.s8.s8.s32 "
        "{%0,%1,%2,%3}, {%4,%5,%6,%7}, {%8,%9}, {%0,%1,%2,%3};"
        : "+r"(c[0]), "+r"(c[1]), "+r"(c[2]), "+r"(c[3])
        : "r"(a[0]), "r"(a[1]), "r"(a[2]), "r"(a[3]), "r"(b0), "r"(b1));
}

// ---------------- exact pow2-ceil scale (matches jnp.exp2(ceil(log2(s)))) ----
__device__ __forceinline__ float pow2_scale(float amax) {
    float s = fmaxf(amax / 127.0f, 1e-30f);
    int e;
    float f = frexpf(s, &e);  // s = f * 2^e, f in [0.5, 1)
    return ldexpf(1.0f, (f == 0.5f) ? (e - 1) : e);
}

// ---------------- kernel 1: zero colmax ----------------
__global__ void k_zero() {
    int i = blockIdx.x * blockDim.x + threadIdx.x;
    if (i < KDIM) { g_xmax[i] = 0.0f; g_wmax[i] = 0.0f; }
}

// ---------------- kernel 2: column absmax ----------------
__global__ void k_colmax(const float* __restrict__ src, int which) {
    int col = blockIdx.x * blockDim.x + threadIdx.x;  // < KDIM
    size_t r0 = (size_t)blockIdx.y * 256;
    const float* p = src + r0 * KDIM + col;
    float m = 0.0f;
#pragma unroll 4
    for (int r = 0; r < 256; r++)
        m = fmaxf(m, fabsf(p[(size_t)r * KDIM]));
    float* dst = which ? g_wmax : g_xmax;
    atomicMax((int*)&dst[col], __float_as_int(m));  // valid: values >= 0
}

// ---------------- kernel 3: smooth scale ----------------
__global__ void k_smooth() {
    int k = blockIdx.x * blockDim.x + threadIdx.x;
    if (k < KDIM) g_smooth[k] = sqrtf(g_xmax[k] * g_wmax[k]);
}

// ---------------- block max reduce (256 threads) ----------------
__device__ __forceinline__ float block_amax(float v, float* sred) {
    int t = threadIdx.x;
#pragma unroll
    for (int o = 16; o; o >>= 1) v = fmaxf(v, __shfl_xor_sync(0xffffffffu, v, o));
    if ((t & 31) == 0) sred[t >> 5] = v;
    __syncthreads();
    if (t == 0) {
        float m = sred[0];
#pragma unroll
        for (int i = 1; i < 8; i++) m = fmaxf(m, sred[i]);
        sred[0] = m;
    }
    __syncthreads();
    return sred[0];
}

__device__ __forceinline__ int8_t q8(float v, float inv) {
    float q = rintf(v * inv);
    q = fminf(fmaxf(q, -127.0f), 127.0f);
    return (int8_t)(int)q;
}

// ---------------- kernel 4: quantize X (one block = one row) ----------------
__global__ void k_quant_x(const float* __restrict__ x) {
    __shared__ float sred[8];
    int row = blockIdx.x;
    int t = threadIdx.x;
    const float4* xr = (const float4*)(x + (size_t)row * KDIM);
    const float4* sm = (const float4*)g_smooth;
    float4 v[4];
    float am = 0.0f;
#pragma unroll
    for (int i = 0; i < 4; i++) {
        int idx = t + 256 * i;
        float4 a = xr[idx];
        float4 s = sm[idx];
        v[i].x = a.x / s.x; v[i].y = a.y / s.y; v[i].z = a.z / s.z; v[i].w = a.w / s.w;
        am = fmaxf(am, fmaxf(fmaxf(fabsf(v[i].x), fabsf(v[i].y)),
                             fmaxf(fabsf(v[i].z), fabsf(v[i].w))));
    }
    float scale = pow2_scale(block_amax(am, sred));
    if (t == 0) g_xs[row] = scale;
    float inv = 1.0f / scale;  // exact (power of two)
    char4* dst = (char4*)(g_xq8 + (size_t)row * KDIM);
#pragma unroll
    for (int i = 0; i < 4; i++) {
        int idx = t + 256 * i;
        char4 c;
        c.x = q8(v[i].x, inv); c.y = q8(v[i].y, inv);
        c.z = q8(v[i].z, inv); c.w = q8(v[i].w, inv);
        dst[idx] = c;
    }
}

// ---------------- kernel 5: quantize W (one block = one row) ----------------
__global__ void k_quant_w(const float* __restrict__ w) {
    __shared__ float sred[8];
    int row = blockIdx.x;
    int t = threadIdx.x;
    const float4* wr = (const float4*)(w + (size_t)row * KDIM);
    const float4* sm = (const float4*)g_smooth;
    float4 v[4];
    float am = 0.0f;
#pragma unroll
    for (int i = 0; i < 4; i++) {
        int idx = t + 256 * i;
        float4 a = wr[idx];
        float4 s = sm[idx];
        v[i].x = a.x * s.x; v[i].y = a.y * s.y; v[i].z = a.z * s.z; v[i].w = a.w * s.w;
        am = fmaxf(am, fmaxf(fmaxf(fabsf(v[i].x), fabsf(v[i].y)),
                             fmaxf(fabsf(v[i].z), fabsf(v[i].w))));
    }
    float scale = pow2_scale(block_amax(am, sred));
    if (t == 0) g_ws[row] = scale;
    float inv = 1.0f / scale;
    char4* dst = (char4*)(g_wq8 + (size_t)row * KDIM);
#pragma unroll
    for (int i = 0; i < 4; i++) {
        int idx = t + 256 * i;
        char4 c;
        c.x = q8(v[i].x, inv); c.y = q8(v[i].y, inv);
        c.z = q8(v[i].z, inv); c.w = q8(v[i].w, inv);
        dst[idx] = c;
    }
}

// ---------------- kernel 6: int8 IMMA GEMM ----------------
// 256 threads = 8 warps (2 m x 4 n), warp tile 64x32, CTA tile 128x128x(K=128/stage).
__global__ void __launch_bounds__(256, 1) k_gemm(const float* __restrict__ bias,
                                                 float* __restrict__ out) {
    extern __shared__ char smem[];
    uint32_t sb = smem_u32(smem);
    int tid = threadIdx.x;
    int wid = tid >> 5, lane = tid & 31;
    int wm = wid & 1, wn = wid >> 1;

    // tile rasterization: groups of 16 m-tiles
    int bid = blockIdx.x;
    int group = bid / (16 * NT_N);
    int rem = bid % (16 * NT_N);
    int mt = group * 16 + (rem & 15);
    int nt = rem >> 4;

    const int8_t* Ab = g_xq8 + (size_t)mt * BM * KDIM;
    const int8_t* Bb = g_wq8 + (size_t)nt * BN * KDIM;

    // per-thread cp.async chunk mapping (1024 16B-chunks per operand per stage)
    uint32_t sofsA[4], sofsB[4];
    uint32_t gofs[4];
#pragma unroll
    for (int i = 0; i < 4; i++) {
        int q = tid + 256 * i;
        int r = q >> 3, c = q & 7;
        gofs[i] = (uint32_t)(r * KDIM + c * 16);
        uint32_t s = (uint32_t)(r * 128 + ((c ^ (r & 7)) << 4));
        sofsA[i] = s;
        sofsB[i] = s;
    }

    auto issue_stage = [&](int s, int kt) {
        uint32_t base = sb + s * STG_BYTES;
        uint32_t koff = kt * BK;
#pragma unroll
        for (int i = 0; i < 4; i++)
            cp_async16(base + sofsA[i], Ab + gofs[i] + koff);
#pragma unroll
        for (int i = 0; i < 4; i++)
            cp_async16(base + A_ST + sofsB[i], Bb + gofs[i] + koff);
        CP_COMMIT();
    };

    // prologue: stages 0..2
    issue_stage(0, 0);
    issue_stage(1, 1);
    issue_stage(2, 2);

    int acc[4][4][4];
#pragma unroll
    for (int a = 0; a < 4; a++)
#pragma unroll
        for (int b = 0; b < 4; b++)
#pragma unroll
            for (int c = 0; c < 4; c++) acc[a][b][c] = 0;

    int lrow = lane & 15;
    int lhi = lane >> 4;

    for (int kt = 0; kt < KTILES; kt++) {
        CP_WAIT(2);
        __syncthreads();
        if (kt + 3 < KTILES) issue_stage((kt + 3) & 3, kt + 3);

        uint32_t As = sb + (kt & 3) * STG_BYTES;
        uint32_t Bs = As + A_ST;
        // per-lane swizzled ldmatrix addressing
        uint32_t aRow = (uint32_t)(wm * 64 + lrow);
        uint32_t bRow = (uint32_t)(wn * 32 + lrow);
        uint32_t sw = (uint32_t)(lrow & 7);

#pragma unroll
        for (int ks = 0; ks < 4; ks++) {
            uint32_t c = (uint32_t)(ks * 2 + lhi);
            uint32_t a[4][4];
#pragma unroll
            for (int mf = 0; mf < 4; mf++) {
                uint32_t addr = As + (aRow + mf * 16) * 128 + ((c ^ sw) << 4);
                ldm_x4(a[mf][0], a[mf][1], a[mf][2], a[mf][3], addr);
            }
            uint32_t b0[4], b1[4];  // b0/b1 per nfrag
#pragma unroll
            for (int j = 0; j < 2; j++) {
                uint32_t t0, t1, t2, t3;
                uint32_t addr = Bs + (bRow + j * 16) * 128 + ((c ^ sw) << 4);
                ldm_x4(t0, t1, t2, t3, addr);
                b0[2 * j] = t0; b1[2 * j] = t2;
                b0[2 * j + 1] = t1; b1[2 * j + 1] = t3;
            }
#pragma unroll
            for (int mf = 0; mf < 4; mf++)
#pragma unroll
                for (int nf = 0; nf < 4; nf++)
                    imma16832(acc[mf][nf], a[mf], b0[nf], b1[nf]);
        }
    }

    // epilogue: out = acc * xs[m] * ws[n] + bias[n]
    int mbase = mt * BM + wm * 64 + (lane >> 2);
    int nbase = nt * BN + wn * 32 + (lane & 3) * 2;
#pragma unroll
    for (int mf = 0; mf < 4; mf++) {
        int m0 = mbase + mf * 16;
        int m1 = m0 + 8;
        float xs0 = g_xs[m0], xs1 = g_xs[m1];
        float* o0 = out + (size_t)m0 * NDIM;
        float* o1 = out + (size_t)m1 * NDIM;
#pragma unroll
        for (int nf = 0; nf < 4; nf++) {
            int n = nbase + nf * 8;
            float ws0 = g_ws[n], ws1 = g_ws[n + 1];
            float bb0 = bias[n], bb1 = bias[n + 1];
            float2 r0, r1;
            r0.x = (float)acc[mf][nf][0] * xs0 * ws0 + bb0;
            r0.y = (float)acc[mf][nf][1] * xs0 * ws1 + bb1;
            r1.x = (float)acc[mf][nf][2] * xs1 * ws0 + bb0;
            r1.y = (float)acc[mf][nf][3] * xs1 * ws1 + bb1;
            *(float2*)(o0 + n) = r0;
            *(float2*)(o1 + n) = r1;
        }
    }
}

// ---------------- launch ----------------
extern "C" void kernel_launch(void* const* d_in, const int* in_sizes, int n_in,
                              void* d_out, int out_size) {
    const float* x = (const float*)d_in[0];     // [M, K]
    const float* w = (const float*)d_in[1];     // [N, K]
    const float* bias = (const float*)d_in[2];  // [N]
    float* out = (float*)d_out;                 // [M, N]

    k_zero<<<KDIM / 256, 256>>>();
    k_colmax<<<dim3(KDIM / 256, MDIM / 256), 256>>>(x, 0);
    k_colmax<<<dim3(KDIM / 256, NDIM / 256), 256>>>(w, 1);
    k_smooth<<<KDIM / 256, 256>>>();
    k_quant_x<<<MDIM, 256>>>(x);
    k_quant_w<<<NDIM, 256>>>(w);

    cudaFuncSetAttribute(k_gemm, cudaFuncAttributeMaxDynamicSharedMemorySize, SMEM_TOTAL);
    k_gemm<<<NT_M * NT_N, 256, SMEM_TOTAL>>>(bias, out);
}